// round 8
// baseline (speedup 1.0000x reference)
#include <cuda_runtime.h>
#include <cstdint>

// out[r,c] = sign(r) * x_real[r,c]   (real-part coercion; rel_err=0.0 confirmed)
// sign(r) = -1 iff ( popc(r & (r>>1)) + ((r & 1) & (r >> 12)) ) is odd.
//
// R8: de-confound R7. Exact-cover grid (no predicates/selects), MLP=4
// front-batched float4 loads, pow2 row-divide as shift. Streaming hints kept.

static constexpr unsigned N_WIRES = 13;

__device__ __forceinline__ float row_sign(unsigned row) {
    unsigned parity = __popc(row & (row >> 1)) + ((row & 1u) & (row >> (N_WIRES - 1)));
    return (parity & 1u) ? -1.0f : 1.0f;
}

// Exact cover: grid*256*4 float4s, block covers 1024 consecutive float4s.
// vec_per_row is a power of two -> row = i >> row_shift.
__global__ __launch_bounds__(256) void cz_real_vec4(
    const float4* __restrict__ xr,
    float4* __restrict__ out,
    unsigned row_shift)        // log2(batch/4)
{
    unsigned base = blockIdx.x * 1024u + threadIdx.x;
    unsigned i0 = base;
    unsigned i1 = base + 256u;
    unsigned i2 = base + 512u;
    unsigned i3 = base + 768u;

    // Front-batched independent loads (MLP=4), evict-first.
    float4 v0 = __ldcs(&xr[i0]);
    float4 v1 = __ldcs(&xr[i1]);
    float4 v2 = __ldcs(&xr[i2]);
    float4 v3 = __ldcs(&xr[i3]);

    float s0 = row_sign(i0 >> row_shift);
    float s1 = row_sign(i1 >> row_shift);
    float s2 = row_sign(i2 >> row_shift);
    float s3 = row_sign(i3 >> row_shift);

    v0.x *= s0; v0.y *= s0; v0.z *= s0; v0.w *= s0;
    v1.x *= s1; v1.y *= s1; v1.z *= s1; v1.w *= s1;
    v2.x *= s2; v2.y *= s2; v2.z *= s2; v2.w *= s2;
    v3.x *= s3; v3.y *= s3; v3.z *= s3; v3.w *= s3;

    __stcs(&out[i0], v0);
    __stcs(&out[i1], v1);
    __stcs(&out[i2], v2);
    __stcs(&out[i3], v3);
}

// Scalar path: tail elements [start, n) or full problem for odd shapes.
__global__ __launch_bounds__(256) void cz_real_scalar(
    const float* __restrict__ xr,
    float* __restrict__ out,
    unsigned start, unsigned n_elems, unsigned batch)
{
    unsigned i = start + blockIdx.x * 256u + threadIdx.x;
    if (i >= n_elems) return;
    float s = row_sign(i / batch);
    out[i] = s * xr[i];
}

extern "C" void kernel_launch(void* const* d_in, const int* in_sizes, int n_in,
                              void* d_out, int out_size)
{
    if (n_in < 1) return;
    const void* xr = d_in[0];

    unsigned E = (unsigned)out_size;
    if ((unsigned)in_sizes[0] < E) E = (unsigned)in_sizes[0];
    if (E == 0) return;

    unsigned batch = E >> N_WIRES;          // columns (4096 nominally)
    if (batch == 0) batch = 1;

    bool pow2_batch4 = (batch % 4u == 0) &&
                       (((batch / 4u) & (batch / 4u - 1u)) == 0);
    bool vec_ok =
        (((uintptr_t)xr) % 16u == 0) &&
        (((uintptr_t)d_out) % 16u == 0) &&
        pow2_batch4 && (E % 4u == 0);

    if (vec_ok) {
        unsigned vpr = batch / 4u;
        unsigned row_shift = 0;
        while ((1u << row_shift) < vpr) row_shift++;   // log2, vpr is pow2

        unsigned n_vec = E / 4u;                       // 2^23 nominally
        unsigned full_blocks = n_vec / 1024u;          // 8192 nominally
        if (full_blocks)
            cz_real_vec4<<<full_blocks, 256>>>(
                (const float4*)xr, (float4*)d_out, row_shift);

        unsigned done = full_blocks * 1024u * 4u;      // floats covered
        if (done < E)                                   // tail (none nominally)
            cz_real_scalar<<<((E - done) + 255u) / 256u, 256>>>(
                (const float*)xr, (float*)d_out, done, E, batch);
    } else {
        cz_real_scalar<<<(E + 255u) / 256u, 256>>>(
            (const float*)xr, (float*)d_out, 0, E, batch);
    }
}

// round 9
// speedup vs baseline: 1.0299x; 1.0299x over previous
#include <cuda_runtime.h>
#include <cstdint>

// out[r,c] = sign(r) * x_real[r,c]   (real-part coercion; rel_err=0.0 confirmed)
// sign(r) = -1 iff ( popc(r & (r>>1)) + ((r & 1) & (r >> 12)) ) is odd.
//
// R9: R7/R8 post-mortem isolated __ldcs/__stcs as the regression (L1 40->64%,
// DRAM 72.8->68.5%). Revert to plain LDG/STG (R6's memory behavior), keep
// exact-cover grid + shift-based row index, MLP=2.

static constexpr unsigned N_WIRES = 13;

__device__ __forceinline__ float row_sign(unsigned row) {
    unsigned parity = __popc(row & (row >> 1)) + ((row & 1u) & (row >> (N_WIRES - 1)));
    return (parity & 1u) ? -1.0f : 1.0f;
}

// Exact cover: each block owns 512 consecutive float4s; thread t handles
// base+t and base+256+t. No bounds checks (host guarantees divisibility).
__global__ __launch_bounds__(256) void cz_real_v2(
    const float4* __restrict__ xr,
    float4* __restrict__ out,
    unsigned row_shift)        // log2(batch/4)
{
    unsigned i0 = blockIdx.x * 512u + threadIdx.x;
    unsigned i1 = i0 + 256u;

    float4 v0 = xr[i0];
    float4 v1 = xr[i1];

    float s0 = row_sign(i0 >> row_shift);
    float s1 = row_sign(i1 >> row_shift);

    v0.x *= s0; v0.y *= s0; v0.z *= s0; v0.w *= s0;
    v1.x *= s1; v1.y *= s1; v1.z *= s1; v1.w *= s1;

    out[i0] = v0;
    out[i1] = v1;
}

// Scalar path: tail [start, n) or full problem for odd shapes/alignment.
__global__ __launch_bounds__(256) void cz_real_scalar(
    const float* __restrict__ xr,
    float* __restrict__ out,
    unsigned start, unsigned n_elems, unsigned batch)
{
    unsigned i = start + blockIdx.x * 256u + threadIdx.x;
    if (i >= n_elems) return;
    float s = row_sign(i / batch);
    out[i] = s * xr[i];
}

extern "C" void kernel_launch(void* const* d_in, const int* in_sizes, int n_in,
                              void* d_out, int out_size)
{
    if (n_in < 1) return;
    const void* xr = d_in[0];

    unsigned E = (unsigned)out_size;
    if ((unsigned)in_sizes[0] < E) E = (unsigned)in_sizes[0];
    if (E == 0) return;

    unsigned batch = E >> N_WIRES;          // columns (4096 nominally)
    if (batch == 0) batch = 1;

    bool pow2_batch4 = (batch % 4u == 0) &&
                       (((batch / 4u) & (batch / 4u - 1u)) == 0);
    bool vec_ok =
        (((uintptr_t)xr) % 16u == 0) &&
        (((uintptr_t)d_out) % 16u == 0) &&
        pow2_batch4 && (E % 4u == 0);

    if (vec_ok) {
        unsigned vpr = batch / 4u;                    // 1024 nominally
        unsigned row_shift = 0;
        while ((1u << row_shift) < vpr) row_shift++;  // log2 (vpr is pow2)

        unsigned n_vec = E / 4u;                      // 2^23 nominally
        unsigned full_blocks = n_vec / 512u;          // 16384 nominally
        if (full_blocks)
            cz_real_v2<<<full_blocks, 256>>>(
                (const float4*)xr, (float4*)d_out, row_shift);

        unsigned done = full_blocks * 512u * 4u;      // floats covered
        if (done < E)                                  // tail (none nominally)
            cz_real_scalar<<<((E - done) + 255u) / 256u, 256>>>(
                (const float*)xr, (float*)d_out, done, E, batch);
    } else {
        cz_real_scalar<<<(E + 255u) / 256u, 256>>>(
            (const float*)xr, (float*)d_out, 0, E, batch);
    }
}